// round 1
// baseline (speedup 1.0000x reference)
#include <cuda_runtime.h>
#include <cstdint>

// RWKV7 chunked attention, B=4 T=2048 H=32 C=64 dT=16.
// One CTA per (b,h) sequence; sequential scan over NT=128 chunks.

#define B_ 4
#define T_ 2048
#define H_ 32
#define C_ 64
#define DT_ 16
#define NT_ (T_ / DT_)
#define THREADS 256
#define CP (C_ + 1)   // padded row stride to avoid bank conflicts

__global__ __launch_bounds__(THREADS, 1)
void rwkv7_kernel(const float* __restrict__ gw, const float* __restrict__ gq,
                  const float* __restrict__ gk, const float* __restrict__ gv,
                  const float* __restrict__ ga, const float* __restrict__ gb,
                  const float* __restrict__ gs0, float* __restrict__ gy)
{
    const int bh = blockIdx.x;
    const int b = bh / H_;
    const int h = bh % H_;
    const int tid = threadIdx.x;

    __shared__ float st[C_][CP];        // state[i][j]
    __shared__ float s_wq[DT_][CP];
    __shared__ float s_wa[DT_][CP];
    __shared__ float s_kwi[DT_][CP];
    __shared__ float s_bwi[DT_][CP];
    __shared__ float s_v[DT_][CP];
    __shared__ float s_u[DT_][CP];      // holds ab_u then u
    __shared__ float s_ab[DT_][DT_];
    __shared__ float s_ak[DT_][DT_];
    __shared__ float s_qb[DT_][DT_];
    __shared__ float s_qk[DT_][DT_];
    __shared__ float s_fw[C_];

    // init state from s0[b][h][i][j]
    {
        const float* s0p = gs0 + (size_t)(b * H_ + h) * C_ * C_;
        for (int idx = tid; idx < C_ * C_; idx += THREADS) {
            st[idx >> 6][idx & 63] = s0p[idx];
        }
    }
    __syncthreads();

    const size_t stride_t = (size_t)H_ * C_;   // stride between consecutive time steps

    for (int ch = 0; ch < NT_; ch++) {
        const int t0 = ch * DT_;

        // ---- step 1: per-column decay cumprod + scaled tiles (64 threads) ----
        if (tid < C_) {
            const int c = tid;
            size_t base = (((size_t)b * T_ + t0) * H_ + h) * C_ + c;
            float p = 1.0f;
            #pragma unroll
            for (int t = 0; t < DT_; t++) {
                size_t idx = base + (size_t)t * stride_t;
                float wv = gw[idx];
                float wd = __expf(-__expf(wv));
                float p_prev = p;           // incl/wd = cumprod up to t-1
                p *= wd;
                float inv = 1.0f / p;
                s_wq[t][c]  = gq[idx] * p;
                s_wa[t][c]  = ga[idx] * p_prev;
                s_kwi[t][c] = gk[idx] * inv;
                s_bwi[t][c] = gb[idx] * inv;
                s_v[t][c]   = gv[idx];
            }
            s_fw[c] = p;
        }
        __syncthreads();

        // ---- step 2: Gram matrices ab, ak, qb, qk (256 threads, one (t,s) each) ----
        {
            const int t = tid >> 4;
            const int s = tid & 15;
            float ab = 0.f, ak = 0.f, qb = 0.f, qk = 0.f;
            #pragma unroll
            for (int c = 0; c < C_; c++) {
                float wa = s_wa[t][c], wq = s_wq[t][c];
                float bw = s_bwi[s][c], kw = s_kwi[s][c];
                ab += wa * bw;
                ak += wa * kw;
                qb += wq * bw;
                qk += wq * kw;
            }
            float strict = (t > s)  ? 1.f : 0.f;
            float inclm  = (t >= s) ? 1.f : 0.f;
            s_ab[t][s] = ab * strict;
            s_ak[t][s] = ak * strict;
            s_qb[t][s] = qb * inclm;
            s_qk[t][s] = qk * inclm;
        }
        __syncthreads();

        // ---- step 3: ab_u[t][i] = ak@v + wa@state  (4 i-values per thread) ----
        {
            const int t  = tid >> 4;
            const int j0 = tid & 15;
            float acc[4] = {0.f, 0.f, 0.f, 0.f};
            #pragma unroll
            for (int s = 0; s < DT_; s++) {
                float aks = s_ak[t][s];
                #pragma unroll
                for (int r = 0; r < 4; r++) acc[r] += aks * s_v[s][j0 + 16 * r];
            }
            #pragma unroll
            for (int j = 0; j < C_; j++) {
                float waj = s_wa[t][j];
                #pragma unroll
                for (int r = 0; r < 4; r++) acc[r] += waj * st[j0 + 16 * r][j];
            }
            #pragma unroll
            for (int r = 0; r < 4; r++) s_u[t][j0 + 16 * r] = acc[r];
        }
        __syncthreads();

        // ---- step 4: forward substitution (I - ab) u = ab_u, per-column, regs ----
        if (tid < C_) {
            const int c = tid;
            float u[DT_];
            #pragma unroll
            for (int t = 0; t < DT_; t++) {
                float acc = s_u[t][c];
                #pragma unroll
                for (int s = 0; s < DT_; s++) {
                    if (s < t) acc += s_ab[t][s] * u[s];
                }
                u[t] = acc;
            }
            #pragma unroll
            for (int t = 0; t < DT_; t++) s_u[t][c] = u[t];
        }
        __syncthreads();

        // ---- step 5: y[t][i] = qk@v + qb@u + wq@state ----
        {
            const int t  = tid >> 4;
            const int j0 = tid & 15;
            float acc[4] = {0.f, 0.f, 0.f, 0.f};
            #pragma unroll
            for (int s = 0; s < DT_; s++) {
                float qks = s_qk[t][s];
                float qbs = s_qb[t][s];
                #pragma unroll
                for (int r = 0; r < 4; r++) {
                    int i = j0 + 16 * r;
                    acc[r] += qks * s_v[s][i] + qbs * s_u[s][i];
                }
            }
            #pragma unroll
            for (int j = 0; j < C_; j++) {
                float wqj = s_wq[t][j];
                #pragma unroll
                for (int r = 0; r < 4; r++) acc[r] += wqj * st[j0 + 16 * r][j];
            }
            size_t ybase = (((size_t)b * T_ + t0 + t) * H_ + h) * C_;
            #pragma unroll
            for (int r = 0; r < 4; r++) gy[ybase + j0 + 16 * r] = acc[r];
        }
        __syncthreads();   // state reads in steps 3/5 done before update

        // ---- step 6: state[i][j] = state*fw[j] + (v^T kwi + u^T bwi) * fw[j] ----
        {
            for (int idx = tid; idx < C_ * C_; idx += THREADS) {
                const int i = idx >> 6;
                const int j = idx & 63;
                float fwj = s_fw[j];
                float accv = 0.f, accu = 0.f;
                #pragma unroll
                for (int t = 0; t < DT_; t++) {
                    accv += s_v[t][i] * s_kwi[t][j];
                    accu += s_u[t][i] * s_bwi[t][j];
                }
                st[i][j] = st[i][j] * fwj + (accv + accu) * fwj;
            }
        }
        __syncthreads();
    }
}

extern "C" void kernel_launch(void* const* d_in, const int* in_sizes, int n_in,
                              void* d_out, int out_size)
{
    const float* w  = (const float*)d_in[0];
    const float* q  = (const float*)d_in[1];
    const float* k  = (const float*)d_in[2];
    const float* v  = (const float*)d_in[3];
    const float* a  = (const float*)d_in[4];
    const float* b  = (const float*)d_in[5];
    const float* s0 = (const float*)d_in[6];
    // d_in[7] is dT (compile-time constant 16 here)
    float* y = (float*)d_out;

    rwkv7_kernel<<<B_ * H_, THREADS>>>(w, q, k, v, a, b, s0, y);
}

// round 2
// speedup vs baseline: 3.7810x; 3.7810x over previous
#include <cuda_runtime.h>
#include <cstdint>

// RWKV7 chunked attention, B=4 T=2048 H=32 C=64 dT=16.
// One CTA per (b,h); sequential scan over NT=128 chunks.
// Register-prefetched inputs, float4 shared-memory GEMM phases.

#define B_ 4
#define T_ 2048
#define H_ 32
#define C_ 64
#define DT_ 16
#define NT_ (T_ / DT_)
#define THREADS 256
#define TS 68                   // tile row stride in floats (16B aligned, conflict-free)

// ---- shared memory layout (word offsets into dynamic smem) ----
#define OFF_WQ   0
#define OFF_WA   (OFF_WQ  + DT_ * TS)
#define OFF_KWI  (OFF_WA  + DT_ * TS)
#define OFF_BWI  (OFF_KWI + DT_ * TS)
#define OFF_V    (OFF_BWI + DT_ * TS)
#define OFF_U    (OFF_V   + DT_ * TS)
#define OFF_ABU  (OFF_U   + DT_ * TS)
#define OFF_YP   (OFF_ABU + DT_ * TS)
#define OFF_LP   (OFF_YP  + DT_ * TS)     // [4][TS]
#define OFF_FW   (OFF_LP  + 4 * TS)       // [64]
#define OFF_AB   (OFF_FW  + 64)           // [16][16]
#define OFF_AK   (OFF_AB  + 256)
#define OFF_QB   (OFF_AK  + 256)
#define OFF_QK   (OFF_QB  + 256)
#define OFF_ST   (OFF_QK  + 256)          // [64][TS]
#define SMEM_WORDS (OFF_ST + C_ * TS)
#define SMEM_BYTES (SMEM_WORDS * 4)

__device__ __forceinline__ float4 ld4(const float* p) { return *reinterpret_cast<const float4*>(p); }
__device__ __forceinline__ void st4(float* p, float4 v) { *reinterpret_cast<float4*>(p) = v; }
__device__ __forceinline__ float dot4(float4 a, float4 b) {
    return a.x * b.x + a.y * b.y + a.z * b.z + a.w * b.w;
}

__global__ __launch_bounds__(THREADS, 1)
void rwkv7_kernel(const float* __restrict__ gw, const float* __restrict__ gq,
                  const float* __restrict__ gk, const float* __restrict__ gv,
                  const float* __restrict__ ga, const float* __restrict__ gb,
                  const float* __restrict__ gs0, float* __restrict__ gy)
{
    extern __shared__ float sm[];

    const int bh  = blockIdx.x;
    const int b   = bh / H_;
    const int h   = bh % H_;
    const int tid = threadIdx.x;

    // loader mapping: thread owns column cl, t-group t4 (4 consecutive t)
    const int cl = tid & 63;
    const int t4 = tid >> 6;

    // ---- init state from s0 (float4) ----
    {
        const float* s0p = gs0 + (size_t)bh * C_ * C_;
        #pragma unroll
        for (int q4 = tid; q4 < C_ * C_ / 4; q4 += THREADS) {
            int i  = q4 >> 4;
            int j0 = (q4 & 15) * 4;
            st4(sm + OFF_ST + i * TS + j0, ld4(s0p + i * C_ + j0));
        }
    }

    const size_t stride_t = (size_t)H_ * C_;

    // ---- prefetch registers for chunk 0 ----
    float rw[4], rq[4], rk[4], rv[4], ra[4], rb[4];
    {
        size_t base = (((size_t)b * T_ + t4 * 4) * H_ + h) * C_ + cl;
        #pragma unroll
        for (int r = 0; r < 4; r++) {
            size_t ix = base + (size_t)r * stride_t;
            rw[r] = gw[ix]; rq[r] = gq[ix]; rk[r] = gk[ix];
            rv[r] = gv[ix]; ra[r] = ga[ix]; rb[r] = gb[ix];
        }
    }
    __syncthreads();   // st ready

    for (int ch = 0; ch < NT_; ch++) {
        const int t0 = ch * DT_;

        // ======== phase A: per-thread decay products ========
        float wd[4];
        {
            float lp = 1.0f;
            #pragma unroll
            for (int r = 0; r < 4; r++) {
                float e = __expf(rw[r]);
                wd[r] = __expf(-e);
                lp *= wd[r];
            }
            sm[OFF_LP + t4 * TS + cl] = lp;
        }
        __syncthreads();

        // ======== phase B: prefix across t-groups, scale + stage tiles ========
        {
            float pre = 1.0f;
            #pragma unroll
            for (int g = 0; g < 3; g++)
                if (g < t4) pre *= sm[OFF_LP + g * TS + cl];
            float incl = pre;
            #pragma unroll
            for (int r = 0; r < 4; r++) {
                float ip = incl;          // cumprod up to t-1
                incl *= wd[r];            // inclusive cumprod
                int t = t4 * 4 + r;
                float rinv = __fdividef(1.0f, incl);
                sm[OFF_WQ  + t * TS + cl] = rq[r] * incl;
                sm[OFF_WA  + t * TS + cl] = ra[r] * ip;
                sm[OFF_KWI + t * TS + cl] = rk[r] * rinv;
                sm[OFF_BWI + t * TS + cl] = rb[r] * rinv;
                sm[OFF_V   + t * TS + cl] = rv[r];
            }
            if (t4 == 3) sm[OFF_FW + cl] = incl;   // fw = incl at t=15
        }
        // regs consumed: prefetch next chunk now (hidden behind phases C-F)
        if (ch + 1 < NT_) {
            size_t base = (((size_t)b * T_ + (t0 + DT_) + t4 * 4) * H_ + h) * C_ + cl;
            #pragma unroll
            for (int r = 0; r < 4; r++) {
                size_t ix = base + (size_t)r * stride_t;
                rw[r] = gw[ix]; rq[r] = gq[ix]; rk[r] = gk[ix];
                rv[r] = gv[ix]; ra[r] = ga[ix]; rb[r] = gb[ix];
            }
        }
        __syncthreads();

        // ======== phase C: Gram matrices ab, ak, qb, qk (16x16, depth 64) ========
        {
            const int tg = tid >> 4;
            const int sg = tid & 15;
            const float* war = sm + OFF_WA  + tg * TS;
            const float* wqr = sm + OFF_WQ  + tg * TS;
            const float* bwr = sm + OFF_BWI + sg * TS;
            const float* kwr = sm + OFF_KWI + sg * TS;
            float ab = 0.f, ak = 0.f, qb = 0.f, qk = 0.f;
            #pragma unroll
            for (int c4 = 0; c4 < 16; c4++) {
                float4 A = ld4(war + 4 * c4);
                float4 Q = ld4(wqr + 4 * c4);
                float4 Bv = ld4(bwr + 4 * c4);
                float4 Kv = ld4(kwr + 4 * c4);
                ab += dot4(A, Bv);
                ak += dot4(A, Kv);
                qb += dot4(Q, Bv);
                qk += dot4(Q, Kv);
            }
            float mstr = (tg > sg)  ? 1.f : 0.f;
            float minc = (tg >= sg) ? 1.f : 0.f;
            sm[OFF_AB + tg * 16 + sg] = ab * mstr;
            sm[OFF_AK + tg * 16 + sg] = ak * mstr;
            sm[OFF_QB + tg * 16 + sg] = qb * minc;
            sm[OFF_QK + tg * 16 + sg] = qk * minc;
        }
        __syncthreads();

        // ======== phase D: abu = ak@v + wa@S^T ; yp = qk@v + wq@S^T ========
        {
            const int tg = tid >> 4;
            const int ig = tid & 15;          // i = ig + 16*r (strided ownership)
            float aa[4] = {0.f, 0.f, 0.f, 0.f};
            float ay[4] = {0.f, 0.f, 0.f, 0.f};
            const float* war = sm + OFF_WA + tg * TS;
            const float* wqr = sm + OFF_WQ + tg * TS;
            #pragma unroll
            for (int j4 = 0; j4 < 16; j4++) {
                float4 A = ld4(war + 4 * j4);
                float4 Q = ld4(wqr + 4 * j4);
                #pragma unroll
                for (int r = 0; r < 4; r++) {
                    float4 s = ld4(sm + OFF_ST + (ig + 16 * r) * TS + 4 * j4);
                    aa[r] += dot4(A, s);
                    ay[r] += dot4(Q, s);
                }
            }
            #pragma unroll
            for (int s = 0; s < 16; s++) {
                float aks = sm[OFF_AK + tg * 16 + s];
                float qks = sm[OFF_QK + tg * 16 + s];
                #pragma unroll
                for (int r = 0; r < 4; r++) {
                    float vv = sm[OFF_V + s * TS + ig + 16 * r];
                    aa[r] += aks * vv;
                    ay[r] += qks * vv;
                }
            }
            #pragma unroll
            for (int r = 0; r < 4; r++) {
                sm[OFF_ABU + tg * TS + ig + 16 * r] = aa[r];
                sm[OFF_YP  + tg * TS + ig + 16 * r] = ay[r];
            }
        }
        __syncthreads();

        // ======== phase E: forward substitution u = (I-ab)^{-1} abu ========
        if (tid < C_) {
            const int c = tid;
            float uu[DT_];
            #pragma unroll
            for (int t = 0; t < DT_; t++) uu[t] = sm[OFF_ABU + t * TS + c];
            #pragma unroll
            for (int t = 1; t < DT_; t++) {
                float acc = uu[t];
                #pragma unroll
                for (int s = 0; s < DT_; s++)
                    if (s < t) acc += sm[OFF_AB + t * 16 + s] * uu[s];
                uu[t] = acc;
            }
            #pragma unroll
            for (int t = 0; t < DT_; t++) sm[OFF_U + t * TS + c] = uu[t];
        }
        __syncthreads();

        // ======== phase F: y output + state update ========
        // F1: y[t][i] = yp[t][i] + qb@u
        {
            const int tg = tid >> 4;
            const int i0 = (tid & 15) * 4;
            float4 acc = ld4(sm + OFF_YP + tg * TS + i0);
            #pragma unroll
            for (int s = 0; s < 16; s++) {
                float qbs = sm[OFF_QB + tg * 16 + s];
                float4 u4 = ld4(sm + OFF_U + s * TS + i0);
                acc.x += qbs * u4.x; acc.y += qbs * u4.y;
                acc.z += qbs * u4.z; acc.w += qbs * u4.w;
            }
            size_t yb = (((size_t)b * T_ + t0 + tg) * H_ + h) * C_ + i0;
            st4(gy + yb, acc);
        }
        // F2: st = (st + v^T kwi + u^T bwi) * fw[j]   (4x4 register tile)
        {
            const int i0 = (tid >> 4) * 4;
            const int j0 = (tid & 15) * 4;
            float4 a0 = {0,0,0,0}, a1 = {0,0,0,0}, a2 = {0,0,0,0}, a3 = {0,0,0,0};
            #pragma unroll
            for (int t = 0; t < DT_; t++) {
                float4 v4 = ld4(sm + OFF_V   + t * TS + i0);
                float4 u4 = ld4(sm + OFF_U   + t * TS + i0);
                float4 kw = ld4(sm + OFF_KWI + t * TS + j0);
                float4 bw = ld4(sm + OFF_BWI + t * TS + j0);
                a0.x += v4.x * kw.x + u4.x * bw.x; a0.y += v4.x * kw.y + u4.x * bw.y;
                a0.z += v4.x * kw.z + u4.x * bw.z; a0.w += v4.x * kw.w + u4.x * bw.w;
                a1.x += v4.y * kw.x + u4.y * bw.x; a1.y += v4.y * kw.y + u4.y * bw.y;
                a1.z += v4.y * kw.z + u4.y * bw.z; a1.w += v4.y * kw.w + u4.y * bw.w;
                a2.x += v4.z * kw.x + u4.z * bw.x; a2.y += v4.z * kw.y + u4.z * bw.y;
                a2.z += v4.z * kw.z + u4.z * bw.z; a2.w += v4.z * kw.w + u4.z * bw.w;
                a3.x += v4.w * kw.x + u4.w * bw.x; a3.y += v4.w * kw.y + u4.w * bw.y;
                a3.z += v4.w * kw.z + u4.w * bw.z; a3.w += v4.w * kw.w + u4.w * bw.w;
            }
            float4 fw4 = ld4(sm + OFF_FW + j0);
            float4 accs[4] = {a0, a1, a2, a3};
            #pragma unroll
            for (int r = 0; r < 4; r++) {
                float* sp = sm + OFF_ST + (i0 + r) * TS + j0;
                float4 s = ld4(sp);
                s.x = (s.x + accs[r].x) * fw4.x;
                s.y = (s.y + accs[r].y) * fw4.y;
                s.z = (s.z + accs[r].z) * fw4.z;
                s.w = (s.w + accs[r].w) * fw4.w;
                st4(sp, s);
            }
        }
        __syncthreads();
    }
}

extern "C" void kernel_launch(void* const* d_in, const int* in_sizes, int n_in,
                              void* d_out, int out_size)
{
    const float* w  = (const float*)d_in[0];
    const float* q  = (const float*)d_in[1];
    const float* k  = (const float*)d_in[2];
    const float* v  = (const float*)d_in[3];
    const float* a  = (const float*)d_in[4];
    const float* b  = (const float*)d_in[5];
    const float* s0 = (const float*)d_in[6];
    float* y = (float*)d_out;

    cudaFuncSetAttribute(rwkv7_kernel, cudaFuncAttributeMaxDynamicSharedMemorySize, SMEM_BYTES);
    rwkv7_kernel<<<B_ * H_, THREADS, SMEM_BYTES>>>(w, q, k, v, a, b, s0, y);
}

// round 3
// speedup vs baseline: 3.9197x; 1.0367x over previous
#include <cuda_runtime.h>
#include <cstdint>

// RWKV7 chunked attention, B=4 T=2048 H=32 C=64 dT=16.
// One CTA (512 thr) per (b,h); warp-specialized intervals + f32x2 packed FMA.

#define B_ 4
#define T_ 2048
#define H_ 32
#define C_ 64
#define DT_ 16
#define NT_ (T_ / DT_)
#define THREADS 512

typedef unsigned long long u64;

// ---- shared layout (float words) ----
#define OFF_WQ   0
#define OFF_WA   1024
#define OFF_KWI  2048
#define OFF_BWI  3072
#define OFF_V    4096
#define OFF_U    5120
#define OFF_ABU  6144
#define OFF_AB   7168     // [16][16] masked
#define OFF_QB   7424     // [16][16] masked
#define OFF_AKQK 7680     // [16][16] float2 (ak,qk) masked
#define OFF_LP   8192     // [8][64]
#define OFF_FW   8704     // [64]
#define OFF_ST   8768     // [64][64] swizzled
#define SMEM_WORDS (OFF_ST + 4096)
#define SMEM_BYTES (SMEM_WORDS * 4)

// xor swizzle: tiles [16][64]: float4-group f stored at f^row; st [64][64]: f^(row>>2)
__device__ __forceinline__ int tile_off(int row, int f) {       // float4-aligned word offset
    return row * 64 + (((f ^ row) & 15) << 2);
}
__device__ __forceinline__ int tile_w(int row, int c) {         // scalar word offset
    return row * 64 + ((((c >> 2) ^ row) & 15) << 2) + (c & 3);
}
__device__ __forceinline__ int st_off(int row, int f) {
    return row * 64 + (((f ^ (row >> 2)) & 15) << 2);
}

__device__ __forceinline__ float4 ld4(const float* p) { return *reinterpret_cast<const float4*>(p); }
__device__ __forceinline__ void st4(float* p, float4 v) { *reinterpret_cast<float4*>(p) = v; }
__device__ __forceinline__ ulonglong2 ldp(const float* p) { return *reinterpret_cast<const ulonglong2*>(p); }
__device__ __forceinline__ void stp(float* p, ulonglong2 v) { *reinterpret_cast<ulonglong2*>(p) = v; }

__device__ __forceinline__ u64 pk2(float lo, float hi) {
    u64 r; asm("mov.b64 %0, {%1, %2};" : "=l"(r) : "f"(lo), "f"(hi)); return r;
}
__device__ __forceinline__ void un2(u64 v, float& lo, float& hi) {
    asm("mov.b64 {%0, %1}, %2;" : "=f"(lo), "=f"(hi) : "l"(v));
}
__device__ __forceinline__ void fma2(u64& d, u64 a, u64 b) {
    asm("fma.rn.f32x2 %0, %1, %2, %0;" : "+l"(d) : "l"(a), "l"(b));
}
__device__ __forceinline__ u64 add2(u64 a, u64 b) {
    u64 d; asm("add.rn.f32x2 %0, %1, %2;" : "=l"(d) : "l"(a), "l"(b)); return d;
}
__device__ __forceinline__ u64 mul2(u64 a, u64 b) {
    u64 d; asm("mul.rn.f32x2 %0, %1, %2;" : "=l"(d) : "l"(a), "l"(b)); return d;
}

__global__ __launch_bounds__(THREADS, 1)
void rwkv7_kernel(const float* __restrict__ gw, const float* __restrict__ gq,
                  const float* __restrict__ gk, const float* __restrict__ gv,
                  const float* __restrict__ ga, const float* __restrict__ gb,
                  const float* __restrict__ gs0, float* __restrict__ gy)
{
    extern __shared__ float sm[];

    const int bh  = blockIdx.x;
    const int b   = bh / H_;
    const int h   = bh % H_;
    const int tid = threadIdx.x;

    // loader mapping: 8 t-pairs x 64 columns
    const int t2 = tid >> 6;       // 0..7, owns t = 2*t2, 2*t2+1
    const int cl = tid & 63;

    // X-group mapping (tid<256): warp w: 4 t's x 8 i-quads
    const int w    = tid >> 5;
    const int ihx  = (w >> 2) & 1;
    const int tbx  = (w & 3) * 4;
    const int tx   = tbx + ((tid >> 3) & 3);     // t for X thread
    const int iqx  = ihx * 8 + (tid & 7);        // i-quad 0..15
    // Y-group mapping (tid>=256): g = tid-256: (tg|ti = g>>4, sg|tj = g&15)
    const int g    = tid & 255;
    const int tgy  = g >> 4;
    const int sgy  = g & 15;

    // ---- init state ----
    {
        const float* s0p = gs0 + (size_t)bh * C_ * C_;
        #pragma unroll
        for (int q4 = tid; q4 < 1024; q4 += THREADS) {
            int row = q4 >> 4, f = q4 & 15;
            st4(sm + OFF_ST + st_off(row, f), ld4(s0p + row * 64 + f * 4));
        }
    }

    const size_t stride_t = (size_t)H_ * C_;

    // prefetch chunk 0
    float rw[2], rq[2], rk[2], rv[2], ra[2], rb[2];
    {
        size_t base = (((size_t)b * T_ + 2 * t2) * H_ + h) * C_ + cl;
        #pragma unroll
        for (int r = 0; r < 2; r++) {
            size_t ix = base + (size_t)r * stride_t;
            rw[r] = gw[ix]; rq[r] = gq[ix]; rk[r] = gk[ix];
            rv[r] = gv[ix]; ra[r] = ga[ix]; rb[r] = gb[ix];
        }
    }
    __syncthreads();

    for (int ch = 0; ch < NT_; ch++) {
        const int t0 = ch * DT_;

        // ===== A: local decay products =====
        float wd[2];
        {
            wd[0] = __expf(-__expf(rw[0]));
            wd[1] = __expf(-__expf(rw[1]));
            sm[OFF_LP + t2 * 64 + cl] = wd[0] * wd[1];
        }
        __syncthreads();

        // ===== B: prefix, scale, stage tiles; prefetch next =====
        {
            float pre = 1.0f;
            #pragma unroll
            for (int gg = 0; gg < 7; gg++)
                if (gg < t2) pre *= sm[OFF_LP + gg * 64 + cl];
            float incl = pre;
            #pragma unroll
            for (int r = 0; r < 2; r++) {
                int t = 2 * t2 + r;
                float ip = incl;
                incl *= wd[r];
                float rinv = __fdividef(1.0f, incl);
                int tw = tile_w(t, cl);
                sm[OFF_WQ  + tw] = rq[r] * incl;
                sm[OFF_WA  + tw] = ra[r] * ip;
                sm[OFF_KWI + tw] = rk[r] * rinv;
                sm[OFF_BWI + tw] = rb[r] * rinv;
                sm[OFF_V   + tw] = rv[r];
            }
            if (t2 == 7) sm[OFF_FW + cl] = incl;
        }
        if (ch + 1 < NT_) {
            size_t base = (((size_t)b * T_ + (t0 + DT_) + 2 * t2) * H_ + h) * C_ + cl;
            #pragma unroll
            for (int r = 0; r < 2; r++) {
                size_t ix = base + (size_t)r * stride_t;
                rw[r] = gw[ix]; rq[r] = gq[ix]; rk[r] = gk[ix];
                rv[r] = gv[ix]; ra[r] = ga[ix]; rb[r] = gb[ix];
            }
        }
        __syncthreads();

        // persistent across intervals
        float yp[4];                 // X: y partials
        u64 accY[4][2];              // Y: state-update accumulators (v^T kwi then + u^T bwi)

        // ===== interval 3 =====
        if (tid < 256) {
            // X: aa = wa@S^T ; ay = wq@S^T   (t = tx, i = 4*iqx .. +3)
            u64 aa2[4] = {0,0,0,0}, ay2[4] = {0,0,0,0};
            #pragma unroll
            for (int j4 = 0; j4 < 16; j4++) {
                int tf = ((j4 ^ tx) & 15) << 2;
                ulonglong2 A = ldp(sm + OFF_WA + tx * 64 + tf);
                ulonglong2 Q = ldp(sm + OFF_WQ + tx * 64 + tf);
                int sf = ((j4 ^ iqx) & 15) << 2;
                #pragma unroll
                for (int r = 0; r < 4; r++) {
                    ulonglong2 S = ldp(sm + OFF_ST + (4 * iqx + r) * 64 + sf);
                    fma2(aa2[r], A.x, S.x); fma2(aa2[r], A.y, S.y);
                    fma2(ay2[r], Q.x, S.x); fma2(ay2[r], Q.y, S.y);
                }
            }
            // repack (aa, ay) horizontally into (abu-partial, yp) pairs
            u64 ayp[4];
            #pragma unroll
            for (int r = 0; r < 4; r++) {
                float l0, h0, l1, h1;
                un2(aa2[r], l0, h0); un2(ay2[r], l1, h1);
                ayp[r] = pk2(l0 + h0, l1 + h1);
            }
            __syncthreads();   // bar3: grams ready

            // ===== interval 4 (X): += (ak,qk)@v ; store abu, keep yp =====
            #pragma unroll
            for (int s = 0; s < 16; s++) {
                u64 akqk = *reinterpret_cast<const u64*>(sm + OFF_AKQK + (tx * 16 + s) * 2);
                float4 v4 = ld4(sm + OFF_V + tile_off(s, iqx));
                fma2(ayp[0], akqk, pk2(v4.x, v4.x));
                fma2(ayp[1], akqk, pk2(v4.y, v4.y));
                fma2(ayp[2], akqk, pk2(v4.z, v4.z));
                fma2(ayp[3], akqk, pk2(v4.w, v4.w));
            }
            float abu[4];
            #pragma unroll
            for (int r = 0; r < 4; r++) un2(ayp[r], abu[r], yp[r]);
            st4(sm + OFF_ABU + tile_off(tx, iqx),
                make_float4(abu[0], abu[1], abu[2], abu[3]));
        } else {
            // Y: grams (tg = tgy, sg = sgy)
            u64 ab2 = 0, ak2 = 0, qb2 = 0, qk2 = 0;
            #pragma unroll
            for (int c4 = 0; c4 < 16; c4++) {
                int ftg = ((c4 ^ tgy) & 15) << 2;
                int fsg = ((c4 ^ sgy) & 15) << 2;
                ulonglong2 A  = ldp(sm + OFF_WA  + tgy * 64 + ftg);
                ulonglong2 Q  = ldp(sm + OFF_WQ  + tgy * 64 + ftg);
                ulonglong2 Bv = ldp(sm + OFF_BWI + sgy * 64 + fsg);
                ulonglong2 Kv = ldp(sm + OFF_KWI + sgy * 64 + fsg);
                fma2(ab2, A.x, Bv.x); fma2(ab2, A.y, Bv.y);
                fma2(ak2, A.x, Kv.x); fma2(ak2, A.y, Kv.y);
                fma2(qb2, Q.x, Bv.x); fma2(qb2, Q.y, Bv.y);
                fma2(qk2, Q.x, Kv.x); fma2(qk2, Q.y, Kv.y);
            }
            float l, hi2, ab, ak, qb, qk;
            un2(ab2, l, hi2); ab = l + hi2;
            un2(ak2, l, hi2); ak = l + hi2;
            un2(qb2, l, hi2); qb = l + hi2;
            un2(qk2, l, hi2); qk = l + hi2;
            float mstr = (tgy > sgy)  ? 1.f : 0.f;
            float minc = (tgy >= sgy) ? 1.f : 0.f;
            sm[OFF_AB + tgy * 16 + sgy] = ab * mstr;
            sm[OFF_QB + tgy * 16 + sgy] = qb * minc;
            *reinterpret_cast<u64*>(sm + OFF_AKQK + (tgy * 16 + sgy) * 2) =
                pk2(ak * mstr, qk * minc);

            // Y: accv = v^T kwi  (tile i0=4*tgy, j0=4*sgy)
            #pragma unroll
            for (int r = 0; r < 4; r++) { accY[r][0] = 0; accY[r][1] = 0; }
            #pragma unroll
            for (int t = 0; t < DT_; t++) {
                float4 v4 = ld4(sm + OFF_V + tile_off(t, tgy));
                ulonglong2 K2 = ldp(sm + OFF_KWI + t * 64 + (((sgy ^ t) & 15) << 2));
                u64 v0 = pk2(v4.x, v4.x), v1 = pk2(v4.y, v4.y);
                u64 v2 = pk2(v4.z, v4.z), v3 = pk2(v4.w, v4.w);
                fma2(accY[0][0], v0, K2.x); fma2(accY[0][1], v0, K2.y);
                fma2(accY[1][0], v1, K2.x); fma2(accY[1][1], v1, K2.y);
                fma2(accY[2][0], v2, K2.x); fma2(accY[2][1], v2, K2.y);
                fma2(accY[3][0], v3, K2.x); fma2(accY[3][1], v3, K2.y);
            }
            __syncthreads();   // bar3 (Y side)
        }
        __syncthreads();       // bar4: abu complete

        // ===== interval 5: solve (I-ab) u = abu, threads 0..63 =====
        if (tid < 64) {
            const int c = tid;
            float uu[DT_];
            #pragma unroll
            for (int t = 0; t < DT_; t++)
                uu[t] = sm[OFF_ABU + tile_w(t, c)];
            #pragma unroll
            for (int t = 1; t < DT_; t++) {
                float a0 = uu[t], a1 = 0.f;
                #pragma unroll
                for (int s = 0; s < DT_; s++) {
                    if (s < t) {
                        float p = sm[OFF_AB + t * 16 + s] * uu[s];
                        if (s & 1) a1 += p; else a0 += p;
                    }
                }
                uu[t] = a0 + a1;
            }
            #pragma unroll
            for (int t = 0; t < DT_; t++)
                sm[OFF_U + tile_w(t, c)] = uu[t];
        }
        __syncthreads();       // bar5: u ready

        // ===== interval 6 =====
        if (tid < 256) {
            // X: y = yp + qb@u, store to gmem
            u64 y01 = pk2(yp[0], yp[1]);
            u64 y23 = pk2(yp[2], yp[3]);
            #pragma unroll
            for (int s = 0; s < 16; s++) {
                float qbs = sm[OFF_QB + tx * 16 + s];
                ulonglong2 U2 = ldp(sm + OFF_U + tile_off(s, iqx));
                u64 q2 = pk2(qbs, qbs);
                fma2(y01, q2, U2.x);
                fma2(y23, q2, U2.y);
            }
            float o0, o1, o2, o3;
            un2(y01, o0, o1); un2(y23, o2, o3);
            size_t yb = (((size_t)b * T_ + t0 + tx) * H_ + h) * C_ + 4 * iqx;
            st4(gy + yb, make_float4(o0, o1, o2, o3));
        } else {
            // Y: accu += u^T bwi ; st = (st + acc) * fw
            #pragma unroll
            for (int t = 0; t < DT_; t++) {
                float4 u4 = ld4(sm + OFF_U + tile_off(t, tgy));
                ulonglong2 B2 = ldp(sm + OFF_BWI + t * 64 + (((sgy ^ t) & 15) << 2));
                u64 u0 = pk2(u4.x, u4.x), u1 = pk2(u4.y, u4.y);
                u64 u2 = pk2(u4.z, u4.z), u3 = pk2(u4.w, u4.w);
                fma2(accY[0][0], u0, B2.x); fma2(accY[0][1], u0, B2.y);
                fma2(accY[1][0], u1, B2.x); fma2(accY[1][1], u1, B2.y);
                fma2(accY[2][0], u2, B2.x); fma2(accY[2][1], u2, B2.y);
                fma2(accY[3][0], u3, B2.x); fma2(accY[3][1], u3, B2.y);
            }
            ulonglong2 FWp = ldp(sm + OFF_FW + 4 * sgy);
            #pragma unroll
            for (int r = 0; r < 4; r++) {
                float* sp = sm + OFF_ST + (4 * tgy + r) * 64 + (((sgy ^ tgy) & 15) << 2);
                ulonglong2 S = ldp(sp);
                ulonglong2 Sn;
                Sn.x = mul2(add2(S.x, accY[r][0]), FWp.x);
                Sn.y = mul2(add2(S.y, accY[r][1]), FWp.y);
                stp(sp, Sn);
            }
        }
        __syncthreads();       // bar6: st updated
    }
}

extern "C" void kernel_launch(void* const* d_in, const int* in_sizes, int n_in,
                              void* d_out, int out_size)
{
    const float* w  = (const float*)d_in[0];
    const float* q  = (const float*)d_in[1];
    const float* k  = (const float*)d_in[2];
    const float* v  = (const float*)d_in[3];
    const float* a  = (const float*)d_in[4];
    const float* b  = (const float*)d_in[5];
    const float* s0 = (const float*)d_in[6];
    float* y = (float*)d_out;

    cudaFuncSetAttribute(rwkv7_kernel, cudaFuncAttributeMaxDynamicSharedMemorySize, SMEM_BYTES);
    rwkv7_kernel<<<B_ * H_, THREADS, SMEM_BYTES>>>(w, q, k, v, a, b, s0, y);
}